// round 10
// baseline (speedup 1.0000x reference)
#include <cuda_runtime.h>

// RSI fused single pass, v10. out[c] = g/(g+l) over 13-wide window of
// positive/negative relative deltas (0 when no losses in window).
//
// v8 skeleton (fastest so far). Store-path surgery: s-shifted quad-skewed
// ov transpose -> aligned STG.128 + LDS.128 (saves ~20 L1 wavefronts/warp);
// publish only p[0..11] (p[12..15] never read). R9 lessons: no launch_bounds
// cap, no in-loop LDS staging (occupancy was not the binding constraint).

#define NROWS  2048
#define NCOLS  8192
#define TPB    256
#define ITEMS  16
#define WTILE  512
#define TILE   4096
#define MAXW   64
#define SLOTP  12                 // p floats per lane actually shared
#define PREG   400                // 12*32 + 12 halo -> padded
#define OREG   640                // 4 * h(127)=158 quads -> 636 -> padded

__device__ __forceinline__ int hq(int q) { return q + (q >> 2); }   // quad skew

// Window computation + s-aligned store path. S = (4 - A0%4) & 3, compile-time.
template <int S>
__device__ __forceinline__ void window_store(
    const float* p, const float* n,
    float* ow, float* rout,
    int wbase, int out_cols, int lane, bool edge)
{
    float* myq = ow + 20 * lane;          // 4*hq(4*lane): thread's 4 quads
    float Sw = 0.0f, L = 0.0f;
    float ql[ITEMS], ov4[4];

    #pragma unroll
    for (int j = 0; j < ITEMS + 12; ++j) {
        if (j < ITEMS) ql[j] = L;
        const float vj = (j < ITEMS) ? p[j] : n[j - ITEMS];
        L += fmaxf(-vj, 0.0f);            // exact loss prefix (bitwise l==0)
        Sw += vj;
        if (j >= 13) Sw -= p[j - 13];     // sliding signed window
        if (j >= 12) {
            const int k = j - 12;         // thread-local output idx 0..15
            const float l = L - ql[k];
            const float t = Sw + l;       // g = S + l
            const float o = (l != 0.0f) ? __fdividef(t, t + l) : 0.0f;

            if (k < S) {                                   // head (S values)
                if (lane == 0) rout[wbase + k] = o;        // direct, in-range
                else           myq[k - S - 4] = o;         // prev quad tail
            } else if (k <= ((S == 0) ? 15 : S + 11)) {    // full quads
                ov4[(k - S) & 3] = o;
                if (((k - S) & 3) == 3)
                    *(float4*)(myq + (k - S - 3)) =
                        make_float4(ov4[0], ov4[1], ov4[2], ov4[3]);
            } else {                                       // tail (4-S values)
                if (lane == 31) {
                    const int col = wbase + 496 + k;
                    if (col < out_cols) rout[col] = o;
                } else {
                    myq[k - S] = o;                        // own quad-3 head
                }
            }
        }
    }
    __syncwarp();

    if (!edge) {
        #pragma unroll
        for (int m = 0; m < 4; ++m) {
            const int q = lane + 32 * m;
            if (S == 0 || q < 127) {                        // q=127 partial if S!=0
                const float4 f = *(const float4*)(ow + 4 * hq(q));
                *(float4*)(rout + wbase + S + 4 * q) = f;   // aligned STG.128
            }
        }
    } else {
        const int nvalid = out_cols - wbase;
        #pragma unroll
        for (int m = 0; m < ITEMS; ++m) {
            const int d = lane + 32 * m;                    // o - S
            const int o = S + d;
            if (o < nvalid && d < 508)
                rout[wbase + o] = ow[4 * hq(d >> 2) + (d & 3)];
        }
    }
}

__global__ __launch_bounds__(TPB) void rsi_v10(
    const float* __restrict__ in,
    float* __restrict__ out,
    int out_cols)
{
    __shared__ __align__(16) float s_p[8 * PREG];
    __shared__ __align__(16) float s_o[8 * OREG];

    const int tid   = threadIdx.x;
    const int lane  = tid & 31;
    const int wrp   = tid >> 5;
    const int row   = blockIdx.y;
    const int wbase = blockIdx.x * TILE + wrp * WTILE;
    const float* rin = in + (size_t)row * NCOLS;
    float* pw = s_p + wrp * PREG;
    float* ow = s_o + wrp * OREG;

    const bool edge = (wbase + WTILE) > out_cols;        // last warp of the row

    // ---- load own 16 inputs (non-edge: wbase+512 <= out_cols < NCOLS) ----
    const int g0 = wbase + ITEMS * lane;                 // <= 8188? g0+15 <= 8191 ok
    const float4 xA = *(const float4*)(rin + g0);
    const float4 xB = *(const float4*)(rin + g0 + 4);
    const float4 xC = *(const float4*)(rin + g0 + 8);
    const float4 xD = *(const float4*)(rin + g0 + 12);

    float x16 = __shfl_down_sync(0xffffffffu, xA.x, 1);
    if (lane == 31)
        x16 = (g0 + 16 < NCOLS) ? rin[g0 + 16] : 0.0f;

    float xe = 0.0f;                                     // halo x (lanes 0..12)
    if (lane < 13) {
        const int ge = wbase + WTILE + lane;
        xe = (ge < NCOLS) ? rin[ge] : 0.0f;
    }
    const float xen = __shfl_down_sync(0xffffffffu, xe, 1);

    // ---- own 16 p-values ----
    const float xs[17] = {xA.x, xA.y, xA.z, xA.w, xB.x, xB.y, xB.z, xB.w,
                          xC.x, xC.y, xC.z, xC.w, xD.x, xD.y, xD.z, xD.w, x16};
    float p[ITEMS];
    #pragma unroll
    for (int c = 0; c < ITEMS; ++c) {
        const float prev = xs[c];
        p[c] = (prev != 0.0f) ? __fdividef(xs[c + 1] - prev, prev) : 0.0f;
    }

    // ---- publish p[0..11] only (p[12..15] is never read by neighbors) ----
    float* myp = pw + SLOTP * lane;
    *(float4*)(myp)     = make_float4(p[0], p[1], p[2],  p[3]);
    *(float4*)(myp + 4) = make_float4(p[4], p[5], p[6],  p[7]);
    *(float4*)(myp + 8) = make_float4(p[8], p[9], p[10], p[11]);
    if (lane < 12) {                                     // halo p -> slot 32
        const float pe = (xe != 0.0f) ? __fdividef(xen - xe, xe) : 0.0f;
        pw[SLOTP * 32 + lane] = pe;
    }
    __syncwarp();

    // ---- fetch 12 neighbor p-values (lane 31 hits halo slot) ----
    const float* nb = pw + SLOTP * (lane + 1);
    const float4 n0 = *(const float4*)(nb);
    const float4 n1 = *(const float4*)(nb + 4);
    const float4 n2 = *(const float4*)(nb + 8);
    const float n[12] = {n0.x, n0.y, n0.z, n0.w, n1.x, n1.y, n1.z, n1.w,
                         n2.x, n2.y, n2.z, n2.w};

    // ---- alignment phase for this row (block-uniform) ----
    const unsigned a0 = ((unsigned)row * (unsigned)out_cols) & 3u;
    const int s = (int)((4u - a0) & 3u);
    float* rout = out + (size_t)row * out_cols;

    switch (s) {
        case 0: window_store<0>(p, n, ow, rout, wbase, out_cols, lane, edge); break;
        case 1: window_store<1>(p, n, ow, rout, wbase, out_cols, lane, edge); break;
        case 2: window_store<2>(p, n, ow, rout, wbase, out_cols, lane, edge); break;
        default: window_store<3>(p, n, ow, rout, wbase, out_cols, lane, edge); break;
    }
}

// ---- Generic fallback for unexpected window sizes ----
__global__ __launch_bounds__(TPB) void rsi_generic(
    const float* __restrict__ in,
    float* __restrict__ out,
    int out_cols, int w)
{
    __shared__ float s_in[TPB + MAXW + 1];
    __shared__ float s_g [TPB + MAXW];
    __shared__ float s_l [TPB + MAXW];

    const int row  = blockIdx.y;
    const int base = blockIdx.x * TPB;
    const float* rin = in + (size_t)row * NCOLS;

    const int need_in = TPB + w + 1;
    for (int i = threadIdx.x; i < need_in; i += TPB) {
        const int col = base + i;
        s_in[i] = (col < NCOLS) ? rin[col] : 0.0f;
    }
    __syncthreads();

    const int need_p = TPB + w;
    for (int i = threadIdx.x; i < need_p; i += TPB) {
        const float prev = s_in[i];
        const float cur  = s_in[i + 1];
        const float p = (prev != 0.0f) ? (cur - prev) / prev : 0.0f;
        s_g[i] = fmaxf(p, 0.0f);
        s_l[i] = fmaxf(-p, 0.0f);
    }
    __syncthreads();

    const int c = base + threadIdx.x;
    if (c < out_cols) {
        float g = 0.0f, l = 0.0f;
        for (int j = 0; j < w; ++j) {
            g += s_g[threadIdx.x + j];
            l += s_l[threadIdx.x + j];
        }
        out[(size_t)row * out_cols + c] = (l != 0.0f) ? g / (g + l) : 0.0f;
    }
}

extern "C" void kernel_launch(void* const* d_in, const int* in_sizes, int n_in,
                              void* d_out, int out_size)
{
    const float* in  = (const float*)d_in[0];
    float*       out = (float*)d_out;

    const int out_cols = out_size / NROWS;   // NCOLS - (window_size - 1)
    int w = NCOLS - out_cols;

    if (w == 13) {
        dim3 grid((out_cols + TILE - 1) / TILE, NROWS);
        rsi_v10<<<grid, TPB>>>(in, out, out_cols);
    } else {
        if (w < 1)    w = 1;
        if (w > MAXW) w = MAXW;
        dim3 grid((out_cols + TPB - 1) / TPB, NROWS);
        rsi_generic<<<grid, TPB>>>(in, out, out_cols, w);
    }
}